// round 13
// baseline (speedup 1.0000x reference)
#include <cuda_runtime.h>
#include <cuda_bf16.h>
#include <cuda_fp16.h>
#include <cstdint>

#define NN   4096
#define FF   512
#define UU   64
#define HH   8
#define HU   (HH*UU)     // 512
#define LRELU 0.2f
#define EMAX 256         // max edges/row (mean 42, 33-sigma safe; writes clamped)

// ---------------- scratch ----------------
__device__ __half g_hfeat[NN * HU];           // [N, H*U] fp16, 4 MB (L2-resident)
__device__ float g_fs[NN * HH];
__device__ float g_fn[NN * HH];
__device__ uint32_t g_mask[NN * 128];         // adjacency bitmask, 2 MB
__device__ __nv_bfloat16 g_Xhi[NN * FF];
__device__ __nv_bfloat16 g_Xlo[NN * FF];
__device__ __nv_bfloat16 g_Whi[HU * FF];      // W^T [c][k]
__device__ __nv_bfloat16 g_Wlo[HU * FF];

// ---------------- helpers ----------------
__device__ __forceinline__ uint32_t smem_u32(const void* p) {
    uint32_t a;
    asm("{ .reg .u64 t; cvta.to.shared.u64 t, %1; cvt.u32.u64 %0, t; }" : "=r"(a) : "l"(p));
    return a;
}
__device__ __forceinline__ void ldsm_x4(uint32_t* r, uint32_t addr) {
    asm volatile("ldmatrix.sync.aligned.m8n8.x4.shared.b16 {%0,%1,%2,%3}, [%4];"
        : "=r"(r[0]), "=r"(r[1]), "=r"(r[2]), "=r"(r[3]) : "r"(addr));
}
__device__ __forceinline__ void mma16816(float* c, const uint32_t* a, const uint32_t* b) {
    asm volatile("mma.sync.aligned.m16n8k16.row.col.f32.bf16.bf16.f32 "
        "{%0,%1,%2,%3}, {%4,%5,%6,%7}, {%8,%9}, {%0,%1,%2,%3};"
        : "+f"(c[0]), "+f"(c[1]), "+f"(c[2]), "+f"(c[3])
        : "r"(a[0]), "r"(a[1]), "r"(a[2]), "r"(a[3]), "r"(b[0]), "r"(b[1]));
}
__device__ __forceinline__ void cp16(uint32_t dst, const void* src) {
    asm volatile("cp.async.cg.shared.global [%0], [%1], 16;" :: "r"(dst), "l"(src));
}
#define CP_COMMIT() asm volatile("cp.async.commit_group;" ::: "memory")
#define CP_WAIT1()  asm volatile("cp.async.wait_group 1;" ::: "memory")
#define CP_WAIT0()  asm volatile("cp.async.wait_group 0;" ::: "memory")

// ---------------- preprocess: split X into bf16 hi/lo ----------------
__global__ __launch_bounds__(256)
void split_X_k(const float* __restrict__ X)
{
    int idx = blockIdx.x * 256 + threadIdx.x;
    float4 v = reinterpret_cast<const float4*>(X)[idx];
    __nv_bfloat16 h0 = __float2bfloat16(v.x), h1 = __float2bfloat16(v.y);
    __nv_bfloat16 h2 = __float2bfloat16(v.z), h3 = __float2bfloat16(v.w);
    __nv_bfloat16 l0 = __float2bfloat16(v.x - __bfloat162float(h0));
    __nv_bfloat16 l1 = __float2bfloat16(v.y - __bfloat162float(h1));
    __nv_bfloat16 l2 = __float2bfloat16(v.z - __bfloat162float(h2));
    __nv_bfloat16 l3 = __float2bfloat16(v.w - __bfloat162float(h3));
    __nv_bfloat162* ph = reinterpret_cast<__nv_bfloat162*>(g_Xhi);
    __nv_bfloat162* pl = reinterpret_cast<__nv_bfloat162*>(g_Xlo);
    ph[idx * 2]     = __halves2bfloat162(h0, h1);
    ph[idx * 2 + 1] = __halves2bfloat162(h2, h3);
    pl[idx * 2]     = __halves2bfloat162(l0, l1);
    pl[idx * 2 + 1] = __halves2bfloat162(l2, l3);
}

// ---------------- preprocess: W [H,F,U] -> W^T bf16 hi/lo [c][k] ----------------
__global__ __launch_bounds__(256)
void split_W_k(const float* __restrict__ W)
{
    __shared__ float t[32][33];
    const int k0 = blockIdx.x * 32;
    const int c0 = blockIdx.y * 32;
    const int h  = c0 >> 6;
    const int ub = c0 & 63;
    const int tx = threadIdx.x & 31, ty = threadIdx.x >> 5;

    for (int kk = ty; kk < 32; kk += 8)
        t[kk][tx] = W[(size_t)h * FF * UU + (size_t)(k0 + kk) * UU + ub + tx];
    __syncthreads();
    for (int cc = ty; cc < 32; cc += 8) {
        float v = t[tx][cc];
        __nv_bfloat16 hi = __float2bfloat16(v);
        g_Whi[(size_t)(c0 + cc) * FF + k0 + tx] = hi;
        g_Wlo[(size_t)(c0 + cc) * FF + k0 + tx] = __float2bfloat16(v - __bfloat162float(hi));
    }
}

// ---------------- Kernel 0: A -> bitmask (pure streaming) ----------------
__global__ __launch_bounds__(256)
void build_mask(const float* __restrict__ A)
{
    int gid = blockIdx.x * 256 + threadIdx.x;      // 0 .. NN*128-1
    const float4* p = reinterpret_cast<const float4*>(A) + (size_t)gid * 8;
    uint32_t m = 0;
#pragma unroll
    for (int q = 0; q < 8; q++) {
        float4 v = p[q];
        m |= (uint32_t)(v.x != 0.f) << (q * 4);
        m |= (uint32_t)(v.y != 0.f) << (q * 4 + 1);
        m |= (uint32_t)(v.z != 0.f) << (q * 4 + 2);
        m |= (uint32_t)(v.w != 0.f) << (q * 4 + 3);
    }
    g_mask[gid] = m;
}

// ---------------- Kernel 1: bf16x3 GEMM + fused f_self/f_neigh ----------------
// 512 threads / 16 warps, warp tile 16x32, 3-stage cp.async, 1 barrier/iter.
#define KCHUNK   32
#define ROWB     80
#define A_BYTES  (128 * ROWB)
#define B_BYTES  (64 * ROWB)
#define STAGE_B  (2 * A_BYTES + 2 * B_BYTES)   // 30720
#define NSTAGE   3
#define GEMM_SMEM (NSTAGE * STAGE_B)           // 92160

__global__ __launch_bounds__(512, 2)
void gat_gemm_mma(const float* __restrict__ a_self, const float* __restrict__ a_neigh)
{
    extern __shared__ __align__(16) char dyn[];
    __shared__ float sm_as[UU], sm_an[UU];
    __shared__ float sred_fs[128], sred_fn[128];

    const int tid  = threadIdx.x;
    const int lane = tid & 31, wid = tid >> 5;
    const int bm = blockIdx.x * 128;
    const int hb = blockIdx.y;
    const int bn = hb * 64;
    const int mw = (wid >> 1) * 16;      // warp m offset (16 rows)
    const int nw = (wid & 1) * 32;       // warp n offset (32 cols)

    if (tid < UU) {
        sm_as[tid] = a_self[hb * UU + tid];
        sm_an[tid] = a_neigh[hb * UU + tid];
    }

    const uint32_t sbase = smem_u32(dyn);

    float acc[4][4];
#pragma unroll
    for (int nj = 0; nj < 4; nj++)
#pragma unroll
        for (int q = 0; q < 4; q++) acc[nj][q] = 0.f;

    // loader addressing (512 threads)
    const int a_row = tid >> 2, a_seg = tid & 3;            // A: 128 rows x 4 segs
    const int b_row = (tid & 255) >> 2, b_seg = tid & 3;    // B: 64 rows x 4 segs, hi/lo halves
    // ldmatrix lane addressing
    const int a_r = (lane & 15);
    const int a_k = (lane >> 4) * 8;
    const int b_c = ((lane >> 4) << 3) + (lane & 7);
    const int b_k = ((lane >> 3) & 1) * 8;

    auto issue = [&](int t) {
        const int st = t % NSTAGE;
        const uint32_t pAh = sbase + st * STAGE_B;
        const uint32_t pAl = pAh + A_BYTES;
        const uint32_t pBh = pAl + A_BYTES;
        const uint32_t pBl = pBh + B_BYTES;
        const int kc = t * KCHUNK;
        {
            size_t go = (size_t)(bm + a_row) * FF + kc + a_seg * 8;
            uint32_t so = (uint32_t)(a_row * ROWB + a_seg * 16);
            cp16(pAh + so, g_Xhi + go);
            cp16(pAl + so, g_Xlo + go);
        }
        {
            size_t go = (size_t)(bn + b_row) * FF + kc + b_seg * 8;
            uint32_t so = (uint32_t)(b_row * ROWB + b_seg * 16);
            if (tid < 256) cp16(pBh + so, g_Whi + go);
            else           cp16(pBl + so, g_Wlo + go);
        }
        CP_COMMIT();
    };

    const int T = FF / KCHUNK;    // 16
    issue(0);
    issue(1);
    for (int t = 0; t < T; t++) {
        CP_WAIT1();
        __syncthreads();

        const int st = t % NSTAGE;
        const uint32_t pAh = sbase + st * STAGE_B;
        const uint32_t pAl = pAh + A_BYTES;
        const uint32_t pBh = pAl + A_BYTES;
        const uint32_t pBl = pBh + B_BYTES;

#pragma unroll
        for (int ks = 0; ks < 2; ks++) {
            const int kk = ks * 16;
            uint32_t ah[4], al[4];
            {
                uint32_t ao = (uint32_t)((mw + a_r) * ROWB + (kk + a_k) * 2);
                ldsm_x4(ah, pAh + ao);
                ldsm_x4(al, pAl + ao);
            }
            uint32_t bh[4][2], bl[4][2];
#pragma unroll
            for (int bj = 0; bj < 2; bj++) {
                uint32_t bo = (uint32_t)((nw + bj * 16 + b_c) * ROWB + (kk + b_k) * 2);
                uint32_t r[4];
                ldsm_x4(r, pBh + bo);
                bh[bj * 2][0] = r[0]; bh[bj * 2][1] = r[1];
                bh[bj * 2 + 1][0] = r[2]; bh[bj * 2 + 1][1] = r[3];
                ldsm_x4(r, pBl + bo);
                bl[bj * 2][0] = r[0]; bl[bj * 2][1] = r[1];
                bl[bj * 2 + 1][0] = r[2]; bl[bj * 2 + 1][1] = r[3];
            }
#pragma unroll
            for (int nj = 0; nj < 4; nj++) {
                mma16816(acc[nj], ah, bh[nj]);
                mma16816(acc[nj], ah, bl[nj]);
                mma16816(acc[nj], al, bh[nj]);
            }
        }
        if (t + 2 < T) issue(t + 2);
    }

    // ---- epilogue: store hfeat (fp16) + fused f_self/f_neigh ----
    const int er = lane >> 2;
    const int ec = (lane & 3) * 2;
    {
        const int row = bm + mw + er;
#pragma unroll
        for (int nj = 0; nj < 4; nj++) {
            const int col = bn + nw + nj * 8 + ec;
            *reinterpret_cast<__half2*>(g_hfeat + (size_t)row * HU + col) =
                __floats2half2_rn(acc[nj][0], acc[nj][1]);
            *reinterpret_cast<__half2*>(g_hfeat + (size_t)(row + 8) * HU + col) =
                __floats2half2_rn(acc[nj][2], acc[nj][3]);
        }
    }

    float fsv[2], fnv[2];
    {
        float fs0 = 0.f, fs1 = 0.f, fn0 = 0.f, fn1 = 0.f;
#pragma unroll
        for (int nj = 0; nj < 4; nj++) {
            const int c = nw + nj * 8 + ec;
            float as0 = sm_as[c], as1 = sm_as[c + 1];
            float an0 = sm_an[c], an1 = sm_an[c + 1];
            fs0 += acc[nj][0] * as0 + acc[nj][1] * as1;
            fs1 += acc[nj][2] * as0 + acc[nj][3] * as1;
            fn0 += acc[nj][0] * an0 + acc[nj][1] * an1;
            fn1 += acc[nj][2] * an0 + acc[nj][3] * an1;
        }
        fsv[0] = fs0; fsv[1] = fs1;
        fnv[0] = fn0; fnv[1] = fn1;
    }
#pragma unroll
    for (int rh = 0; rh < 2; rh++) {
        fsv[rh] += __shfl_xor_sync(0xFFFFFFFFu, fsv[rh], 1);
        fsv[rh] += __shfl_xor_sync(0xFFFFFFFFu, fsv[rh], 2);
        fnv[rh] += __shfl_xor_sync(0xFFFFFFFFu, fnv[rh], 1);
        fnv[rh] += __shfl_xor_sync(0xFFFFFFFFu, fnv[rh], 2);
    }
    if (nw == 0 && (lane & 3) == 0) {
        sred_fs[mw + er]     = fsv[0];
        sred_fs[mw + er + 8] = fsv[1];
        sred_fn[mw + er]     = fnv[0];
        sred_fn[mw + er + 8] = fnv[1];
    }
    __syncthreads();
    if (nw == 32 && (lane & 3) == 0) {
#pragma unroll
        for (int rh = 0; rh < 2; rh++) {
            const int r = mw + er + rh * 8;
            g_fs[(size_t)(bm + r) * HH + hb] = sred_fs[r] + fsv[rh];
            g_fn[(size_t)(bm + r) * HH + hb] = sred_fn[r] + fnv[rh];
        }
    }
}

// ---------------- Kernel 3: aggregation (bitmask scan + fp16 gather) ----------------
__global__ __launch_bounds__(128)
void gat_aggregate(const float* __restrict__ bias,
                   float* __restrict__ out)
{
    const int i   = blockIdx.x;
    const int tid = threadIdx.x;            // 0..127
    const int lane = tid & 31, wid = tid >> 5;
    const int h   = tid >> 4;               // head (16 threads per head)
    const int sub = tid & 15;

    __shared__ int   sm_edges[EMAX];        // stores j<<9 (half-unit row offset)
    __shared__ float sm_w[HH][EMAX];
    __shared__ int   sm_psum[4];
    __shared__ float sm_fs[HH];

    if (tid < HH) sm_fs[tid] = g_fs[i * HH + tid];

    // ---- scan: 512 B bitmask per row ----
    uint32_t m = g_mask[i * 128 + tid];
    int cnt = __popc(m);
    int incl = cnt;
#pragma unroll
    for (int o = 1; o < 32; o <<= 1) {
        int nv = __shfl_up_sync(0xFFFFFFFFu, incl, o);
        if (lane >= o) incl += nv;
    }
    if (lane == 31) sm_psum[wid] = incl;
    __syncthreads();
    if (tid == 0) {
        int s = 0;
#pragma unroll
        for (int w = 0; w < 4; w++) { int v = sm_psum[w]; sm_psum[w] = s + v; s += v; }
    }
    __syncthreads();
    {
        int base = (wid ? sm_psum[wid - 1] : 0) + incl - cnt;
        int c0 = tid * 32;
        uint32_t mm = m;
        while (mm) {
            int b = __ffs(mm) - 1;
            mm &= mm - 1;
            sm_edges[min(base, EMAX - 1)] = (c0 + b) << 9;
            base++;
        }
    }
    __syncthreads();
    const int E = min(sm_psum[3], EMAX);

    // ---- weight phase: all E edges, all 8 heads, one pass ----
    for (int e = tid; e < E; e += 128) {
        int j8 = sm_edges[e] >> 6;          // j*8
        float4 f0 = *reinterpret_cast<const float4*>(g_fn + j8);
        float4 f1 = *reinterpret_cast<const float4*>(g_fn + j8 + 4);
        float fn8[8] = {f0.x, f0.y, f0.z, f0.w, f1.x, f1.y, f1.z, f1.w};
#pragma unroll
        for (int hh = 0; hh < HH; hh++) {
            float x = sm_fs[hh] + fn8[hh];
            x = x > 0.f ? x : LRELU * x;
            sm_w[hh][e] = __expf(x);
        }
    }
    __syncthreads();

    // ---- den partials ----
    float den = 0.f;
    for (int e = sub; e < E; e += 16) den += sm_w[h][e];

    // ---- gather-FMA over fp16 rows, unroll 8 ----
    const __half* hb = g_hfeat + tid * 4;   // thread's 4 columns
    float4 acc = make_float4(0.f, 0.f, 0.f, 0.f);
    int e = 0;
    for (; e + 8 <= E; e += 8) {
        int   o[8];
        float w[8];
        uint2 u[8];
#pragma unroll
        for (int q = 0; q < 8; q++) { o[q] = sm_edges[e + q]; w[q] = sm_w[h][e + q]; }
#pragma unroll
        for (int q = 0; q < 8; q++) u[q] = *reinterpret_cast<const uint2*>(hb + o[q]);
#pragma unroll
        for (int q = 0; q < 8; q++) {
            float2 pa = __half22float2(*reinterpret_cast<__half2*>(&u[q].x));
            float2 pb = __half22float2(*reinterpret_cast<__half2*>(&u[q].y));
            acc.x = fmaf(w[q], pa.x, acc.x); acc.y = fmaf(w[q], pa.y, acc.y);
            acc.z = fmaf(w[q], pb.x, acc.z); acc.w = fmaf(w[q], pb.y, acc.w);
        }
    }
    for (; e < E; e++) {
        int o0 = sm_edges[e];
        float w0 = sm_w[h][e];
        uint2 u0 = *reinterpret_cast<const uint2*>(hb + o0);
        float2 pa = __half22float2(*reinterpret_cast<__half2*>(&u0.x));
        float2 pb = __half22float2(*reinterpret_cast<__half2*>(&u0.y));
        acc.x = fmaf(w0, pa.x, acc.x); acc.y = fmaf(w0, pa.y, acc.y);
        acc.z = fmaf(w0, pb.x, acc.z); acc.w = fmaf(w0, pb.y, acc.w);
    }

    // segment-reduce den over the 16 lanes of this head
#pragma unroll
    for (int o = 8; o; o >>= 1) den += __shfl_xor_sync(0xFFFFFFFFu, den, o);
    const float rden = 1.f / den;

    float4 b4 = *reinterpret_cast<const float4*>(bias + tid * 4);
    float4 r;
    r.x = fmaf(acc.x, rden, b4.x); r.y = fmaf(acc.y, rden, b4.y);
    r.z = fmaf(acc.z, rden, b4.z); r.w = fmaf(acc.w, rden, b4.w);
    r.x = r.x > 0.f ? r.x : 0.f;
    r.y = r.y > 0.f ? r.y : 0.f;
    r.z = r.z > 0.f ? r.z : 0.f;
    r.w = r.w > 0.f ? r.w : 0.f;
    *reinterpret_cast<float4*>(out + (size_t)i * HU + tid * 4) = r;
}

// ---------------- launch ----------------
extern "C" void kernel_launch(void* const* d_in, const int* in_sizes, int n_in,
                              void* d_out, int out_size)
{
    const float* X       = (const float*)d_in[0];
    const float* A       = (const float*)d_in[2];
    const float* W       = (const float*)d_in[3];
    const float* a_self  = (const float*)d_in[4];
    const float* a_neigh = (const float*)d_in[5];
    const float* bias    = (const float*)d_in[6];
    float* out = (float*)d_out;

    cudaFuncSetAttribute(gat_gemm_mma, cudaFuncAttributeMaxDynamicSharedMemorySize, GEMM_SMEM);

    build_mask<<<NN * 128 / 256, 256>>>(A);
    split_X_k<<<NN * FF / 4 / 256, 256>>>(X);
    split_W_k<<<dim3(FF / 32, HU / 32), 256>>>(W);
    gat_gemm_mma<<<dim3(NN / 128, HU / 64), 512, GEMM_SMEM>>>(a_self, a_neigh);
    gat_aggregate<<<NN, 128>>>(bias, out);
}

// round 14
// speedup vs baseline: 1.1217x; 1.1217x over previous
#include <cuda_runtime.h>
#include <cuda_bf16.h>
#include <cuda_fp16.h>
#include <cstdint>

#define NN   4096
#define FF   512
#define UU   64
#define HH   8
#define HU   (HH*UU)     // 512
#define LRELU 0.2f
#define EMAX 256         // max edges/row (mean 42, 33-sigma safe; writes clamped)

// ---------------- scratch ----------------
__device__ __half g_hfeat[NN * HU];           // [N, H*U] fp16, 4 MB (L2-resident)
__device__ float g_fs[NN * HH];
__device__ float g_fn[NN * HH];
__device__ uint32_t g_mask[NN * 128];         // adjacency bitmask, 2 MB
__device__ __half g_Xhi[NN * FF];             // X fp16 split hi
__device__ __half g_Xlo[NN * FF];             // X fp16 split lo
__device__ __half g_Wh[HU * FF];              // W^T fp16 [c][k]

// ---------------- helpers ----------------
__device__ __forceinline__ uint32_t smem_u32(const void* p) {
    uint32_t a;
    asm("{ .reg .u64 t; cvta.to.shared.u64 t, %1; cvt.u32.u64 %0, t; }" : "=r"(a) : "l"(p));
    return a;
}
__device__ __forceinline__ void ldsm_x4(uint32_t* r, uint32_t addr) {
    asm volatile("ldmatrix.sync.aligned.m8n8.x4.shared.b16 {%0,%1,%2,%3}, [%4];"
        : "=r"(r[0]), "=r"(r[1]), "=r"(r[2]), "=r"(r[3]) : "r"(addr));
}
__device__ __forceinline__ void mma16816(float* c, const uint32_t* a, const uint32_t* b) {
    asm volatile("mma.sync.aligned.m16n8k16.row.col.f32.f16.f16.f32 "
        "{%0,%1,%2,%3}, {%4,%5,%6,%7}, {%8,%9}, {%0,%1,%2,%3};"
        : "+f"(c[0]), "+f"(c[1]), "+f"(c[2]), "+f"(c[3])
        : "r"(a[0]), "r"(a[1]), "r"(a[2]), "r"(a[3]), "r"(b[0]), "r"(b[1]));
}
__device__ __forceinline__ void cp16(uint32_t dst, const void* src) {
    asm volatile("cp.async.cg.shared.global [%0], [%1], 16;" :: "r"(dst), "l"(src));
}
#define CP_COMMIT() asm volatile("cp.async.commit_group;" ::: "memory")
#define CP_WAIT1()  asm volatile("cp.async.wait_group 1;" ::: "memory")
#define CP_WAIT0()  asm volatile("cp.async.wait_group 0;" ::: "memory")

// ---------------- preprocess: split X into fp16 hi/lo ----------------
__global__ __launch_bounds__(256)
void split_X_k(const float* __restrict__ X)
{
    int idx = blockIdx.x * 256 + threadIdx.x;
    float4 v = reinterpret_cast<const float4*>(X)[idx];
    __half h0 = __float2half_rn(v.x), h1 = __float2half_rn(v.y);
    __half h2 = __float2half_rn(v.z), h3 = __float2half_rn(v.w);
    __half l0 = __float2half_rn(v.x - __half2float(h0));
    __half l1 = __float2half_rn(v.y - __half2float(h1));
    __half l2 = __float2half_rn(v.z - __half2float(h2));
    __half l3 = __float2half_rn(v.w - __half2float(h3));
    __half2* ph = reinterpret_cast<__half2*>(g_Xhi);
    __half2* pl = reinterpret_cast<__half2*>(g_Xlo);
    ph[idx * 2]     = __halves2half2(h0, h1);
    ph[idx * 2 + 1] = __halves2half2(h2, h3);
    pl[idx * 2]     = __halves2half2(l0, l1);
    pl[idx * 2 + 1] = __halves2half2(l2, l3);
}

// ---------------- preprocess: W [H,F,U] -> W^T fp16 [c][k] ----------------
__global__ __launch_bounds__(256)
void split_W_k(const float* __restrict__ W)
{
    __shared__ float t[32][33];
    const int k0 = blockIdx.x * 32;
    const int c0 = blockIdx.y * 32;
    const int h  = c0 >> 6;
    const int ub = c0 & 63;
    const int tx = threadIdx.x & 31, ty = threadIdx.x >> 5;

    for (int kk = ty; kk < 32; kk += 8)
        t[kk][tx] = W[(size_t)h * FF * UU + (size_t)(k0 + kk) * UU + ub + tx];
    __syncthreads();
    for (int cc = ty; cc < 32; cc += 8)
        g_Wh[(size_t)(c0 + cc) * FF + k0 + tx] = __float2half_rn(t[tx][cc]);
}

// ---------------- Kernel 0: A -> bitmask (pure streaming) ----------------
__global__ __launch_bounds__(256)
void build_mask(const float* __restrict__ A)
{
    int gid = blockIdx.x * 256 + threadIdx.x;      // 0 .. NN*128-1
    const float4* p = reinterpret_cast<const float4*>(A) + (size_t)gid * 8;
    uint32_t m = 0;
#pragma unroll
    for (int q = 0; q < 8; q++) {
        float4 v = p[q];
        m |= (uint32_t)(v.x != 0.f) << (q * 4);
        m |= (uint32_t)(v.y != 0.f) << (q * 4 + 1);
        m |= (uint32_t)(v.z != 0.f) << (q * 4 + 2);
        m |= (uint32_t)(v.w != 0.f) << (q * 4 + 3);
    }
    g_mask[gid] = m;
}

// ---------------- Kernel 1: fp16x2 GEMM + fused f_self/f_neigh ----------------
// 512 threads / 16 warps, warp tile 16x32, 3-stage cp.async, 2-ahead prefetch.
#define KCHUNK   32
#define ROWB     80
#define A_BYTES  (128 * ROWB)                  // 10240
#define B_BYTES  (64 * ROWB)                   // 5120
#define STAGE_B  (2 * A_BYTES + B_BYTES)       // 25600
#define NSTAGE   3
#define GEMM_SMEM (NSTAGE * STAGE_B)           // 76800

__global__ __launch_bounds__(512, 2)
void gat_gemm_mma(const float* __restrict__ a_self, const float* __restrict__ a_neigh)
{
    extern __shared__ __align__(16) char dyn[];
    __shared__ float sm_as[UU], sm_an[UU];
    __shared__ float sred_fs[128], sred_fn[128];

    const int tid  = threadIdx.x;
    const int lane = tid & 31, wid = tid >> 5;
    const int bm = blockIdx.x * 128;
    const int hb = blockIdx.y;
    const int bn = hb * 64;
    const int mw = (wid >> 1) * 16;      // warp m offset (16 rows)
    const int nw = (wid & 1) * 32;       // warp n offset (32 cols)

    if (tid < UU) {
        sm_as[tid] = a_self[hb * UU + tid];
        sm_an[tid] = a_neigh[hb * UU + tid];
    }

    const uint32_t sbase = smem_u32(dyn);

    float acc[4][4];
#pragma unroll
    for (int nj = 0; nj < 4; nj++)
#pragma unroll
        for (int q = 0; q < 4; q++) acc[nj][q] = 0.f;

    // loader addressing (512 threads)
    const int a_row = tid >> 2, a_seg = tid & 3;            // A: 128 rows x 4 segs
    const int b_row = (tid & 255) >> 2, b_seg = tid & 3;    // B: 64 rows x 4 segs (threads <256)
    // ldmatrix lane addressing
    const int a_r = (lane & 15);
    const int a_k = (lane >> 4) * 8;
    const int b_c = ((lane >> 4) << 3) + (lane & 7);
    const int b_k = ((lane >> 3) & 1) * 8;

    auto issue = [&](int t) {
        const int st = t % NSTAGE;
        const uint32_t pAh = sbase + st * STAGE_B;
        const uint32_t pAl = pAh + A_BYTES;
        const uint32_t pB  = pAl + A_BYTES;
        const int kc = t * KCHUNK;
        {
            size_t go = (size_t)(bm + a_row) * FF + kc + a_seg * 8;
            uint32_t so = (uint32_t)(a_row * ROWB + a_seg * 16);
            cp16(pAh + so, g_Xhi + go);
            cp16(pAl + so, g_Xlo + go);
        }
        if (tid < 256) {
            size_t go = (size_t)(bn + b_row) * FF + kc + b_seg * 8;
            uint32_t so = (uint32_t)(b_row * ROWB + b_seg * 16);
            cp16(pB + so, g_Wh + go);
        }
        CP_COMMIT();
    };

    const int T = FF / KCHUNK;    // 16
    issue(0);
    issue(1);
    for (int t = 0; t < T; t++) {
        CP_WAIT1();               // stage t complete
        __syncthreads();          // buffer (t+2)%3 now free (compute of t-1 done)
        if (t + 2 < T) issue(t + 2);

        const int st = t % NSTAGE;
        const uint32_t pAh = sbase + st * STAGE_B;
        const uint32_t pAl = pAh + A_BYTES;
        const uint32_t pB  = pAl + A_BYTES;

#pragma unroll
        for (int ks = 0; ks < 2; ks++) {
            const int kk = ks * 16;
            uint32_t ah[4], al[4];
            {
                uint32_t ao = (uint32_t)((mw + a_r) * ROWB + (kk + a_k) * 2);
                ldsm_x4(ah, pAh + ao);
                ldsm_x4(al, pAl + ao);
            }
            uint32_t bb[4][2];
#pragma unroll
            for (int bj = 0; bj < 2; bj++) {
                uint32_t bo = (uint32_t)((nw + bj * 16 + b_c) * ROWB + (kk + b_k) * 2);
                uint32_t r[4];
                ldsm_x4(r, pB + bo);
                bb[bj * 2][0] = r[0]; bb[bj * 2][1] = r[1];
                bb[bj * 2 + 1][0] = r[2]; bb[bj * 2 + 1][1] = r[3];
            }
#pragma unroll
            for (int nj = 0; nj < 4; nj++) {
                mma16816(acc[nj], ah, bb[nj]);
                mma16816(acc[nj], al, bb[nj]);
            }
        }
    }

    // ---- epilogue: store hfeat (fp16) + fused f_self/f_neigh ----
    const int er = lane >> 2;
    const int ec = (lane & 3) * 2;
    {
        const int row = bm + mw + er;
#pragma unroll
        for (int nj = 0; nj < 4; nj++) {
            const int col = bn + nw + nj * 8 + ec;
            *reinterpret_cast<__half2*>(g_hfeat + (size_t)row * HU + col) =
                __floats2half2_rn(acc[nj][0], acc[nj][1]);
            *reinterpret_cast<__half2*>(g_hfeat + (size_t)(row + 8) * HU + col) =
                __floats2half2_rn(acc[nj][2], acc[nj][3]);
        }
    }

    float fsv[2], fnv[2];
    {
        float fs0 = 0.f, fs1 = 0.f, fn0 = 0.f, fn1 = 0.f;
#pragma unroll
        for (int nj = 0; nj < 4; nj++) {
            const int c = nw + nj * 8 + ec;
            float as0 = sm_as[c], as1 = sm_as[c + 1];
            float an0 = sm_an[c], an1 = sm_an[c + 1];
            fs0 += acc[nj][0] * as0 + acc[nj][1] * as1;
            fs1 += acc[nj][2] * as0 + acc[nj][3] * as1;
            fn0 += acc[nj][0] * an0 + acc[nj][1] * an1;
            fn1 += acc[nj][2] * an0 + acc[nj][3] * an1;
        }
        fsv[0] = fs0; fsv[1] = fs1;
        fnv[0] = fn0; fnv[1] = fn1;
    }
#pragma unroll
    for (int rh = 0; rh < 2; rh++) {
        fsv[rh] += __shfl_xor_sync(0xFFFFFFFFu, fsv[rh], 1);
        fsv[rh] += __shfl_xor_sync(0xFFFFFFFFu, fsv[rh], 2);
        fnv[rh] += __shfl_xor_sync(0xFFFFFFFFu, fnv[rh], 1);
        fnv[rh] += __shfl_xor_sync(0xFFFFFFFFu, fnv[rh], 2);
    }
    if (nw == 0 && (lane & 3) == 0) {
        sred_fs[mw + er]     = fsv[0];
        sred_fs[mw + er + 8] = fsv[1];
        sred_fn[mw + er]     = fnv[0];
        sred_fn[mw + er + 8] = fnv[1];
    }
    __syncthreads();
    if (nw == 32 && (lane & 3) == 0) {
#pragma unroll
        for (int rh = 0; rh < 2; rh++) {
            const int r = mw + er + rh * 8;
            g_fs[(size_t)(bm + r) * HH + hb] = sred_fs[r] + fsv[rh];
            g_fn[(size_t)(bm + r) * HH + hb] = sred_fn[r] + fnv[rh];
        }
    }
}

// ---------------- Kernel 3: aggregation (bitmask scan + fp16 gather) ----------------
__global__ __launch_bounds__(128)
void gat_aggregate(const float* __restrict__ bias,
                   float* __restrict__ out)
{
    const int i   = blockIdx.x;
    const int tid = threadIdx.x;            // 0..127
    const int lane = tid & 31, wid = tid >> 5;
    const int h   = tid >> 4;               // head (16 threads per head)
    const int sub = tid & 15;

    __shared__ int   sm_edges[EMAX];        // stores j<<9 (half-unit row offset)
    __shared__ float sm_w[HH][EMAX];
    __shared__ int   sm_psum[4];
    __shared__ float sm_fs[HH];

    if (tid < HH) sm_fs[tid] = g_fs[i * HH + tid];

    // ---- scan: 512 B bitmask per row ----
    uint32_t m = g_mask[i * 128 + tid];
    int cnt = __popc(m);
    int incl = cnt;
#pragma unroll
    for (int o = 1; o < 32; o <<= 1) {
        int nv = __shfl_up_sync(0xFFFFFFFFu, incl, o);
        if (lane >= o) incl += nv;
    }
    if (lane == 31) sm_psum[wid] = incl;
    __syncthreads();
    if (tid == 0) {
        int s = 0;
#pragma unroll
        for (int w = 0; w < 4; w++) { int v = sm_psum[w]; sm_psum[w] = s + v; s += v; }
    }
    __syncthreads();
    {
        int base = (wid ? sm_psum[wid - 1] : 0) + incl - cnt;
        int c0 = tid * 32;
        uint32_t mm = m;
        while (mm) {
            int b = __ffs(mm) - 1;
            mm &= mm - 1;
            sm_edges[min(base, EMAX - 1)] = (c0 + b) << 9;
            base++;
        }
    }
    __syncthreads();
    const int E = min(sm_psum[3], EMAX);

    // ---- weight phase: all E edges, all 8 heads, one pass ----
    for (int e = tid; e < E; e += 128) {
        int j8 = sm_edges[e] >> 6;          // j*8
        float4 f0 = *reinterpret_cast<const float4*>(g_fn + j8);
        float4 f1 = *reinterpret_cast<const float4*>(g_fn + j8 + 4);
        float fn8[8] = {f0.x, f0.y, f0.z, f0.w, f1.x, f1.y, f1.z, f1.w};
#pragma unroll
        for (int hh = 0; hh < HH; hh++) {
            float x = sm_fs[hh] + fn8[hh];
            x = x > 0.f ? x : LRELU * x;
            sm_w[hh][e] = __expf(x);
        }
    }
    __syncthreads();

    // ---- den partials ----
    float den = 0.f;
    for (int e = sub; e < E; e += 16) den += sm_w[h][e];

    // ---- gather-FMA over fp16 rows, unroll 8 ----
    const __half* hb = g_hfeat + tid * 4;   // thread's 4 columns
    float4 acc = make_float4(0.f, 0.f, 0.f, 0.f);
    int e = 0;
    for (; e + 8 <= E; e += 8) {
        int   o[8];
        float w[8];
        uint2 u[8];
#pragma unroll
        for (int q = 0; q < 8; q++) { o[q] = sm_edges[e + q]; w[q] = sm_w[h][e + q]; }
#pragma unroll
        for (int q = 0; q < 8; q++) u[q] = *reinterpret_cast<const uint2*>(hb + o[q]);
#pragma unroll
        for (int q = 0; q < 8; q++) {
            float2 pa = __half22float2(*reinterpret_cast<__half2*>(&u[q].x));
            float2 pb = __half22float2(*reinterpret_cast<__half2*>(&u[q].y));
            acc.x = fmaf(w[q], pa.x, acc.x); acc.y = fmaf(w[q], pa.y, acc.y);
            acc.z = fmaf(w[q], pb.x, acc.z); acc.w = fmaf(w[q], pb.y, acc.w);
        }
    }
    for (; e < E; e++) {
        int o0 = sm_edges[e];
        float w0 = sm_w[h][e];
        uint2 u0 = *reinterpret_cast<const uint2*>(hb + o0);
        float2 pa = __half22float2(*reinterpret_cast<__half2*>(&u0.x));
        float2 pb = __half22float2(*reinterpret_cast<__half2*>(&u0.y));
        acc.x = fmaf(w0, pa.x, acc.x); acc.y = fmaf(w0, pa.y, acc.y);
        acc.z = fmaf(w0, pb.x, acc.z); acc.w = fmaf(w0, pb.y, acc.w);
    }

    // segment-reduce den over the 16 lanes of this head
#pragma unroll
    for (int o = 8; o; o >>= 1) den += __shfl_xor_sync(0xFFFFFFFFu, den, o);
    const float rden = 1.f / den;

    float4 b4 = *reinterpret_cast<const float4*>(bias + tid * 4);
    float4 r;
    r.x = fmaf(acc.x, rden, b4.x); r.y = fmaf(acc.y, rden, b4.y);
    r.z = fmaf(acc.z, rden, b4.z); r.w = fmaf(acc.w, rden, b4.w);
    r.x = r.x > 0.f ? r.x : 0.f;
    r.y = r.y > 0.f ? r.y : 0.f;
    r.z = r.z > 0.f ? r.z : 0.f;
    r.w = r.w > 0.f ? r.w : 0.f;
    *reinterpret_cast<float4*>(out + (size_t)i * HU + tid * 4) = r;
}

// ---------------- launch ----------------
extern "C" void kernel_launch(void* const* d_in, const int* in_sizes, int n_in,
                              void* d_out, int out_size)
{
    const float* X       = (const float*)d_in[0];
    const float* A       = (const float*)d_in[2];
    const float* W       = (const float*)d_in[3];
    const float* a_self  = (const float*)d_in[4];
    const float* a_neigh = (const float*)d_in[5];
    const float* bias    = (const float*)d_in[6];
    float* out = (float*)d_out;

    cudaFuncSetAttribute(gat_gemm_mma, cudaFuncAttributeMaxDynamicSharedMemorySize, GEMM_SMEM);

    build_mask<<<NN * 128 / 256, 256>>>(A);
    split_X_k<<<NN * FF / 4 / 256, 256>>>(X);
    split_W_k<<<dim3(FF / 32, HU / 32), 256>>>(W);
    gat_gemm_mma<<<dim3(NN / 128, HU / 64), 512, GEMM_SMEM>>>(a_self, a_neigh);
    gat_aggregate<<<NN, 128>>>(bias, out);
}

// round 15
// speedup vs baseline: 1.1929x; 1.0634x over previous
#include <cuda_runtime.h>
#include <cuda_bf16.h>
#include <cuda_fp16.h>
#include <cstdint>

#define NN   4096
#define FF   512
#define UU   64
#define HH   8
#define HU   (HH*UU)     // 512
#define LRELU 0.2f
#define EMAX 256         // max edges/row (mean 42, 33-sigma safe; writes clamped)

// ---------------- scratch ----------------
__device__ __half g_hfeat[NN * HU];           // [N, H*U] fp16, 4 MB (L2-resident)
__device__ float g_fs[NN * HH];
__device__ float g_fn[NN * HH];
__device__ uint32_t g_mask[NN * 128];         // adjacency bitmask, 2 MB
__device__ __half g_Xhi[NN * FF];             // X fp16 split hi
__device__ __half g_Xlo[NN * FF];             // X fp16 split lo
__device__ __half g_Wh[HU * FF];              // W^T fp16 [c][k]

// ---------------- helpers ----------------
__device__ __forceinline__ uint32_t smem_u32(const void* p) {
    uint32_t a;
    asm("{ .reg .u64 t; cvta.to.shared.u64 t, %1; cvt.u32.u64 %0, t; }" : "=r"(a) : "l"(p));
    return a;
}
__device__ __forceinline__ void ldsm_x4(uint32_t* r, uint32_t addr) {
    asm volatile("ldmatrix.sync.aligned.m8n8.x4.shared.b16 {%0,%1,%2,%3}, [%4];"
        : "=r"(r[0]), "=r"(r[1]), "=r"(r[2]), "=r"(r[3]) : "r"(addr));
}
__device__ __forceinline__ void mma16816(float* c, const uint32_t* a, const uint32_t* b) {
    asm volatile("mma.sync.aligned.m16n8k16.row.col.f32.f16.f16.f32 "
        "{%0,%1,%2,%3}, {%4,%5,%6,%7}, {%8,%9}, {%0,%1,%2,%3};"
        : "+f"(c[0]), "+f"(c[1]), "+f"(c[2]), "+f"(c[3])
        : "r"(a[0]), "r"(a[1]), "r"(a[2]), "r"(a[3]), "r"(b[0]), "r"(b[1]));
}
__device__ __forceinline__ void cp16(uint32_t dst, const void* src) {
    asm volatile("cp.async.cg.shared.global [%0], [%1], 16;" :: "r"(dst), "l"(src));
}
#define CP_COMMIT() asm volatile("cp.async.commit_group;" ::: "memory")
#define CP_WAIT1()  asm volatile("cp.async.wait_group 1;" ::: "memory")
#define CP_WAIT0()  asm volatile("cp.async.wait_group 0;" ::: "memory")

// ---------------- preprocess: split X into fp16 hi/lo ----------------
__global__ __launch_bounds__(256)
void split_X_k(const float* __restrict__ X)
{
    int idx = blockIdx.x * 256 + threadIdx.x;
    float4 v = reinterpret_cast<const float4*>(X)[idx];
    __half h0 = __float2half_rn(v.x), h1 = __float2half_rn(v.y);
    __half h2 = __float2half_rn(v.z), h3 = __float2half_rn(v.w);
    __half l0 = __float2half_rn(v.x - __half2float(h0));
    __half l1 = __float2half_rn(v.y - __half2float(h1));
    __half l2 = __float2half_rn(v.z - __half2float(h2));
    __half l3 = __float2half_rn(v.w - __half2float(h3));
    __half2* ph = reinterpret_cast<__half2*>(g_Xhi);
    __half2* pl = reinterpret_cast<__half2*>(g_Xlo);
    ph[idx * 2]     = __halves2half2(h0, h1);
    ph[idx * 2 + 1] = __halves2half2(h2, h3);
    pl[idx * 2]     = __halves2half2(l0, l1);
    pl[idx * 2 + 1] = __halves2half2(l2, l3);
}

// ---------------- preprocess: W [H,F,U] -> W^T fp16 [c][k] ----------------
__global__ __launch_bounds__(256)
void split_W_k(const float* __restrict__ W)
{
    __shared__ float t[32][33];
    const int k0 = blockIdx.x * 32;
    const int c0 = blockIdx.y * 32;
    const int h  = c0 >> 6;
    const int ub = c0 & 63;
    const int tx = threadIdx.x & 31, ty = threadIdx.x >> 5;

    for (int kk = ty; kk < 32; kk += 8)
        t[kk][tx] = W[(size_t)h * FF * UU + (size_t)(k0 + kk) * UU + ub + tx];
    __syncthreads();
    for (int cc = ty; cc < 32; cc += 8)
        g_Wh[(size_t)(c0 + cc) * FF + k0 + tx] = __float2half_rn(t[tx][cc]);
}

// ---------------- Kernel 0: A -> bitmask (streaming, PDL primary) ----------------
// 1024 blocks (single wave) x 256 thr, 2 words per thread.
__global__ __launch_bounds__(256)
void build_mask(const float* __restrict__ A)
{
#if __CUDA_ARCH__ >= 900
    cudaTriggerProgrammaticLaunchCompletion();   // let the GEMM launch now
#endif
#pragma unroll
    for (int it = 0; it < 2; it++) {
        int gid = (blockIdx.x * 2 + it) * 256 + threadIdx.x;   // 0 .. NN*128-1
        const float4* p = reinterpret_cast<const float4*>(A) + (size_t)gid * 8;
        uint32_t m = 0;
#pragma unroll
        for (int q = 0; q < 8; q++) {
            float4 v = p[q];
            m |= (uint32_t)(v.x != 0.f) << (q * 4);
            m |= (uint32_t)(v.y != 0.f) << (q * 4 + 1);
            m |= (uint32_t)(v.z != 0.f) << (q * 4 + 2);
            m |= (uint32_t)(v.w != 0.f) << (q * 4 + 3);
        }
        g_mask[gid] = m;
    }
}

// ---------------- Kernel 1: fp16x2 GEMM + fused f_self/f_neigh (PDL secondary) ----------------
// 512 threads / 16 warps, warp tile 16x32, 3-stage cp.async, 2-ahead prefetch.
#define KCHUNK   32
#define ROWB     80
#define A_BYTES  (128 * ROWB)                  // 10240
#define B_BYTES  (64 * ROWB)                   // 5120
#define STAGE_B  (2 * A_BYTES + B_BYTES)       // 25600
#define NSTAGE   3
#define GEMM_SMEM (NSTAGE * STAGE_B)           // 76800

__global__ __launch_bounds__(512, 2)
void gat_gemm_mma(const float* __restrict__ a_self, const float* __restrict__ a_neigh)
{
    extern __shared__ __align__(16) char dyn[];
    __shared__ float sm_as[UU], sm_an[UU];
    __shared__ float sred_fs[128], sred_fn[128];

    const int tid  = threadIdx.x;
    const int lane = tid & 31, wid = tid >> 5;
    const int bm = blockIdx.x * 128;
    const int hb = blockIdx.y;
    const int bn = hb * 64;
    const int mw = (wid >> 1) * 16;      // warp m offset (16 rows)
    const int nw = (wid & 1) * 32;       // warp n offset (32 cols)

    if (tid < UU) {
        sm_as[tid] = a_self[hb * UU + tid];
        sm_an[tid] = a_neigh[hb * UU + tid];
    }

    const uint32_t sbase = smem_u32(dyn);

    float acc[4][4];
#pragma unroll
    for (int nj = 0; nj < 4; nj++)
#pragma unroll
        for (int q = 0; q < 4; q++) acc[nj][q] = 0.f;

    // loader addressing (512 threads)
    const int a_row = tid >> 2, a_seg = tid & 3;            // A: 128 rows x 4 segs
    const int b_row = (tid & 255) >> 2, b_seg = tid & 3;    // B: 64 rows x 4 segs (threads <256)
    // ldmatrix lane addressing
    const int a_r = (lane & 15);
    const int a_k = (lane >> 4) * 8;
    const int b_c = ((lane >> 4) << 3) + (lane & 7);
    const int b_k = ((lane >> 3) & 1) * 8;

    auto issue = [&](int t) {
        const int st = t % NSTAGE;
        const uint32_t pAh = sbase + st * STAGE_B;
        const uint32_t pAl = pAh + A_BYTES;
        const uint32_t pB  = pAl + A_BYTES;
        const int kc = t * KCHUNK;
        {
            size_t go = (size_t)(bm + a_row) * FF + kc + a_seg * 8;
            uint32_t so = (uint32_t)(a_row * ROWB + a_seg * 16);
            cp16(pAh + so, g_Xhi + go);
            cp16(pAl + so, g_Xlo + go);
        }
        if (tid < 256) {
            size_t go = (size_t)(bn + b_row) * FF + kc + b_seg * 8;
            uint32_t so = (uint32_t)(b_row * ROWB + b_seg * 16);
            cp16(pB + so, g_Wh + go);
        }
        CP_COMMIT();
    };

    const int T = FF / KCHUNK;    // 16
    issue(0);
    issue(1);
    for (int t = 0; t < T; t++) {
        CP_WAIT1();               // stage t complete
        __syncthreads();          // buffer (t+2)%3 now free (compute of t-1 done)
        if (t + 2 < T) issue(t + 2);

        const int st = t % NSTAGE;
        const uint32_t pAh = sbase + st * STAGE_B;
        const uint32_t pAl = pAh + A_BYTES;
        const uint32_t pB  = pAl + A_BYTES;

#pragma unroll
        for (int ks = 0; ks < 2; ks++) {
            const int kk = ks * 16;
            uint32_t ah[4], al[4];
            {
                uint32_t ao = (uint32_t)((mw + a_r) * ROWB + (kk + a_k) * 2);
                ldsm_x4(ah, pAh + ao);
                ldsm_x4(al, pAl + ao);
            }
            uint32_t bb[4][2];
#pragma unroll
            for (int bj = 0; bj < 2; bj++) {
                uint32_t bo = (uint32_t)((nw + bj * 16 + b_c) * ROWB + (kk + b_k) * 2);
                uint32_t r[4];
                ldsm_x4(r, pB + bo);
                bb[bj * 2][0] = r[0]; bb[bj * 2][1] = r[1];
                bb[bj * 2 + 1][0] = r[2]; bb[bj * 2 + 1][1] = r[3];
            }
#pragma unroll
            for (int nj = 0; nj < 4; nj++) {
                mma16816(acc[nj], ah, bb[nj]);
                mma16816(acc[nj], al, bb[nj]);
            }
        }
    }

    // ---- epilogue: store hfeat (fp16) + fused f_self/f_neigh ----
    const int er = lane >> 2;
    const int ec = (lane & 3) * 2;
    {
        const int row = bm + mw + er;
#pragma unroll
        for (int nj = 0; nj < 4; nj++) {
            const int col = bn + nw + nj * 8 + ec;
            *reinterpret_cast<__half2*>(g_hfeat + (size_t)row * HU + col) =
                __floats2half2_rn(acc[nj][0], acc[nj][1]);
            *reinterpret_cast<__half2*>(g_hfeat + (size_t)(row + 8) * HU + col) =
                __floats2half2_rn(acc[nj][2], acc[nj][3]);
        }
    }

    float fsv[2], fnv[2];
    {
        float fs0 = 0.f, fs1 = 0.f, fn0 = 0.f, fn1 = 0.f;
#pragma unroll
        for (int nj = 0; nj < 4; nj++) {
            const int c = nw + nj * 8 + ec;
            float as0 = sm_as[c], as1 = sm_as[c + 1];
            float an0 = sm_an[c], an1 = sm_an[c + 1];
            fs0 += acc[nj][0] * as0 + acc[nj][1] * as1;
            fs1 += acc[nj][2] * as0 + acc[nj][3] * as1;
            fn0 += acc[nj][0] * an0 + acc[nj][1] * an1;
            fn1 += acc[nj][2] * an0 + acc[nj][3] * an1;
        }
        fsv[0] = fs0; fsv[1] = fs1;
        fnv[0] = fn0; fnv[1] = fn1;
    }
#pragma unroll
    for (int rh = 0; rh < 2; rh++) {
        fsv[rh] += __shfl_xor_sync(0xFFFFFFFFu, fsv[rh], 1);
        fsv[rh] += __shfl_xor_sync(0xFFFFFFFFu, fsv[rh], 2);
        fnv[rh] += __shfl_xor_sync(0xFFFFFFFFu, fnv[rh], 1);
        fnv[rh] += __shfl_xor_sync(0xFFFFFFFFu, fnv[rh], 2);
    }
    if (nw == 0 && (lane & 3) == 0) {
        sred_fs[mw + er]     = fsv[0];
        sred_fs[mw + er + 8] = fsv[1];
        sred_fn[mw + er]     = fnv[0];
        sred_fn[mw + er + 8] = fnv[1];
    }
    __syncthreads();
    if (nw == 32 && (lane & 3) == 0) {
#pragma unroll
        for (int rh = 0; rh < 2; rh++) {
            const int r = mw + er + rh * 8;
            g_fs[(size_t)(bm + r) * HH + hb] = sred_fs[r] + fsv[rh];
            g_fn[(size_t)(bm + r) * HH + hb] = sred_fn[r] + fnv[rh];
        }
    }

#if __CUDA_ARCH__ >= 900
    // bound build_mask's completion by ours so the downstream aggregate
    // (which reads g_mask) keeps its ordering guarantee.
    cudaGridDependencySynchronize();
#endif
}

// ---------------- Kernel 3: aggregation (bitmask scan + fp16 gather) ----------------
__global__ __launch_bounds__(128)
void gat_aggregate(const float* __restrict__ bias,
                   float* __restrict__ out)
{
    const int i   = blockIdx.x;
    const int tid = threadIdx.x;            // 0..127
    const int lane = tid & 31, wid = tid >> 5;
    const int h   = tid >> 4;               // head (16 threads per head)
    const int sub = tid & 15;

    __shared__ int   sm_edges[EMAX];        // stores j<<9 (half-unit row offset)
    __shared__ float sm_w[HH][EMAX];
    __shared__ int   sm_psum[4];
    __shared__ float sm_fs[HH];

    if (tid < HH) sm_fs[tid] = g_fs[i * HH + tid];

    // ---- scan: 512 B bitmask per row ----
    uint32_t m = g_mask[i * 128 + tid];
    int cnt = __popc(m);
    int incl = cnt;
#pragma unroll
    for (int o = 1; o < 32; o <<= 1) {
        int nv = __shfl_up_sync(0xFFFFFFFFu, incl, o);
        if (lane >= o) incl += nv;
    }
    if (lane == 31) sm_psum[wid] = incl;
    __syncthreads();
    if (tid == 0) {
        int s = 0;
#pragma unroll
        for (int w = 0; w < 4; w++) { int v = sm_psum[w]; sm_psum[w] = s + v; s += v; }
    }
    __syncthreads();
    {
        int base = (wid ? sm_psum[wid - 1] : 0) + incl - cnt;
        int c0 = tid * 32;
        uint32_t mm = m;
        while (mm) {
            int b = __ffs(mm) - 1;
            mm &= mm - 1;
            sm_edges[min(base, EMAX - 1)] = (c0 + b) << 9;
            base++;
        }
    }
    __syncthreads();
    const int E = min(sm_psum[3], EMAX);

    // ---- weight phase: all E edges, all 8 heads, one pass ----
    for (int e = tid; e < E; e += 128) {
        int j8 = sm_edges[e] >> 6;          // j*8
        float4 f0 = *reinterpret_cast<const float4*>(g_fn + j8);
        float4 f1 = *reinterpret_cast<const float4*>(g_fn + j8 + 4);
        float fn8[8] = {f0.x, f0.y, f0.z, f0.w, f1.x, f1.y, f1.z, f1.w};
#pragma unroll
        for (int hh = 0; hh < HH; hh++) {
            float x = sm_fs[hh] + fn8[hh];
            x = x > 0.f ? x : LRELU * x;
            sm_w[hh][e] = __expf(x);
        }
    }
    __syncthreads();

    // ---- den partials ----
    float den = 0.f;
    for (int e = sub; e < E; e += 16) den += sm_w[h][e];

    // ---- gather-FMA over fp16 rows, unroll 8 ----
    const __half* hb = g_hfeat + tid * 4;   // thread's 4 columns
    float4 acc = make_float4(0.f, 0.f, 0.f, 0.f);
    int e = 0;
    for (; e + 8 <= E; e += 8) {
        int   o[8];
        float w[8];
        uint2 u[8];
#pragma unroll
        for (int q = 0; q < 8; q++) { o[q] = sm_edges[e + q]; w[q] = sm_w[h][e + q]; }
#pragma unroll
        for (int q = 0; q < 8; q++) u[q] = *reinterpret_cast<const uint2*>(hb + o[q]);
#pragma unroll
        for (int q = 0; q < 8; q++) {
            float2 pa = __half22float2(*reinterpret_cast<__half2*>(&u[q].x));
            float2 pb = __half22float2(*reinterpret_cast<__half2*>(&u[q].y));
            acc.x = fmaf(w[q], pa.x, acc.x); acc.y = fmaf(w[q], pa.y, acc.y);
            acc.z = fmaf(w[q], pb.x, acc.z); acc.w = fmaf(w[q], pb.y, acc.w);
        }
    }
    for (; e < E; e++) {
        int o0 = sm_edges[e];
        float w0 = sm_w[h][e];
        uint2 u0 = *reinterpret_cast<const uint2*>(hb + o0);
        float2 pa = __half22float2(*reinterpret_cast<__half2*>(&u0.x));
        float2 pb = __half22float2(*reinterpret_cast<__half2*>(&u0.y));
        acc.x = fmaf(w0, pa.x, acc.x); acc.y = fmaf(w0, pa.y, acc.y);
        acc.z = fmaf(w0, pb.x, acc.z); acc.w = fmaf(w0, pb.y, acc.w);
    }

    // segment-reduce den over the 16 lanes of this head
#pragma unroll
    for (int o = 8; o; o >>= 1) den += __shfl_xor_sync(0xFFFFFFFFu, den, o);
    const float rden = 1.f / den;

    float4 b4 = *reinterpret_cast<const float4*>(bias + tid * 4);
    float4 r;
    r.x = fmaf(acc.x, rden, b4.x); r.y = fmaf(acc.y, rden, b4.y);
    r.z = fmaf(acc.z, rden, b4.z); r.w = fmaf(acc.w, rden, b4.w);
    r.x = r.x > 0.f ? r.x : 0.f;
    r.y = r.y > 0.f ? r.y : 0.f;
    r.z = r.z > 0.f ? r.z : 0.f;
    r.w = r.w > 0.f ? r.w : 0.f;
    *reinterpret_cast<float4*>(out + (size_t)i * HU + tid * 4) = r;
}

// ---------------- launch ----------------
extern "C" void kernel_launch(void* const* d_in, const int* in_sizes, int n_in,
                              void* d_out, int out_size)
{
    const float* X       = (const float*)d_in[0];
    const float* A       = (const float*)d_in[2];
    const float* W       = (const float*)d_in[3];
    const float* a_self  = (const float*)d_in[4];
    const float* a_neigh = (const float*)d_in[5];
    const float* bias    = (const float*)d_in[6];
    float* out = (float*)d_out;

    cudaFuncSetAttribute(gat_gemm_mma, cudaFuncAttributeMaxDynamicSharedMemorySize, GEMM_SMEM);

    split_X_k<<<NN * FF / 4 / 256, 256>>>(X);
    split_W_k<<<dim3(FF / 32, HU / 32), 256>>>(W);
    build_mask<<<1024, 256>>>(A);

    // GEMM overlaps build_mask via programmatic dependent launch (no data dep).
    {
        cudaLaunchConfig_t cfg = {};
        cfg.gridDim = dim3(NN / 128, HU / 64, 1);
        cfg.blockDim = dim3(512, 1, 1);
        cfg.dynamicSmemBytes = GEMM_SMEM;
        cfg.stream = 0;
        cudaLaunchAttribute attrs[1];
        attrs[0].id = cudaLaunchAttributeProgrammaticStreamSerialization;
        attrs[0].val.programmaticStreamSerializationAllowed = 1;
        cfg.attrs = attrs;
        cfg.numAttrs = 1;
        cudaLaunchKernelEx(&cfg, gat_gemm_mma, a_self, a_neigh);
    }

    gat_aggregate<<<NN, 128>>>(bias, out);
}

// round 16
// speedup vs baseline: 1.2757x; 1.0695x over previous
#include <cuda_runtime.h>
#include <cuda_bf16.h>
#include <cuda_fp16.h>
#include <cstdint>

#define NN   4096
#define FF   512
#define UU   64
#define HH   8
#define HU   (HH*UU)     // 512
#define LRELU 0.2f
#define EMAX 256         // max edges/row (mean 42, 33-sigma safe; writes clamped)

// ---------------- scratch ----------------
__device__ __half g_hfeat[NN * HU];           // [N, H*U] fp16, 4 MB (L2-resident)
__device__ float g_fs[NN * HH];
__device__ float g_fn[NN * HH];
__device__ uint32_t g_mask[NN * 128];         // adjacency bitmask, 2 MB
__device__ __half g_Xh[NN * FF];              // X fp16
__device__ __half g_Wh[HU * FF];              // W^T fp16 [c][k]

// ---------------- helpers ----------------
__device__ __forceinline__ uint32_t smem_u32(const void* p) {
    uint32_t a;
    asm("{ .reg .u64 t; cvta.to.shared.u64 t, %1; cvt.u32.u64 %0, t; }" : "=r"(a) : "l"(p));
    return a;
}
__device__ __forceinline__ void ldsm_x4(uint32_t* r, uint32_t addr) {
    asm volatile("ldmatrix.sync.aligned.m8n8.x4.shared.b16 {%0,%1,%2,%3}, [%4];"
        : "=r"(r[0]), "=r"(r[1]), "=r"(r[2]), "=r"(r[3]) : "r"(addr));
}
__device__ __forceinline__ void mma16816(float* c, const uint32_t* a, const uint32_t* b) {
    asm volatile("mma.sync.aligned.m16n8k16.row.col.f32.f16.f16.f32 "
        "{%0,%1,%2,%3}, {%4,%5,%6,%7}, {%8,%9}, {%0,%1,%2,%3};"
        : "+f"(c[0]), "+f"(c[1]), "+f"(c[2]), "+f"(c[3])
        : "r"(a[0]), "r"(a[1]), "r"(a[2]), "r"(a[3]), "r"(b[0]), "r"(b[1]));
}
__device__ __forceinline__ void cp16(uint32_t dst, const void* src) {
    asm volatile("cp.async.cg.shared.global [%0], [%1], 16;" :: "r"(dst), "l"(src));
}
#define CP_COMMIT() asm volatile("cp.async.commit_group;" ::: "memory")
#define CP_WAIT1()  asm volatile("cp.async.wait_group 1;" ::: "memory")
#define CP_WAIT0()  asm volatile("cp.async.wait_group 0;" ::: "memory")

// ---------------- preprocess: X -> fp16 ----------------
__global__ __launch_bounds__(256)
void split_X_k(const float* __restrict__ X)
{
    int idx = blockIdx.x * 256 + threadIdx.x;
    float4 v = reinterpret_cast<const float4*>(X)[idx];
    __half2* ph = reinterpret_cast<__half2*>(g_Xh);
    ph[idx * 2]     = __floats2half2_rn(v.x, v.y);
    ph[idx * 2 + 1] = __floats2half2_rn(v.z, v.w);
}

// ---------------- preprocess: W [H,F,U] -> W^T fp16 [c][k] ----------------
__global__ __launch_bounds__(256)
void split_W_k(const float* __restrict__ W)
{
    __shared__ float t[32][33];
    const int k0 = blockIdx.x * 32;
    const int c0 = blockIdx.y * 32;
    const int h  = c0 >> 6;
    const int ub = c0 & 63;
    const int tx = threadIdx.x & 31, ty = threadIdx.x >> 5;

    for (int kk = ty; kk < 32; kk += 8)
        t[kk][tx] = W[(size_t)h * FF * UU + (size_t)(k0 + kk) * UU + ub + tx];
    __syncthreads();
    for (int cc = ty; cc < 32; cc += 8)
        g_Wh[(size_t)(c0 + cc) * FF + k0 + tx] = __float2half_rn(t[tx][cc]);
}

// ---------------- Kernel 0: A -> bitmask (streaming, PDL primary) ----------------
__global__ __launch_bounds__(256)
void build_mask(const float* __restrict__ A)
{
#if __CUDA_ARCH__ >= 900
    cudaTriggerProgrammaticLaunchCompletion();   // let the GEMM launch now
#endif
#pragma unroll
    for (int it = 0; it < 2; it++) {
        int gid = (blockIdx.x * 2 + it) * 256 + threadIdx.x;   // 0 .. NN*128-1
        const float4* p = reinterpret_cast<const float4*>(A) + (size_t)gid * 8;
        uint32_t m = 0;
#pragma unroll
        for (int q = 0; q < 8; q++) {
            float4 v = p[q];
            m |= (uint32_t)(v.x != 0.f) << (q * 4);
            m |= (uint32_t)(v.y != 0.f) << (q * 4 + 1);
            m |= (uint32_t)(v.z != 0.f) << (q * 4 + 2);
            m |= (uint32_t)(v.w != 0.f) << (q * 4 + 3);
        }
        g_mask[gid] = m;
    }
}

// ---------------- Kernel 1: fp16 GEMM + fused f_self/f_neigh (PDL secondary) ----------------
// 512 threads / 16 warps, warp tile 16x32, 3-stage cp.async, 2-ahead prefetch.
#define KCHUNK   32
#define ROWB     80
#define A_BYTES  (128 * ROWB)                  // 10240
#define B_BYTES  (64 * ROWB)                   // 5120
#define STAGE_B  (A_BYTES + B_BYTES)           // 15360
#define NSTAGE   3
#define GEMM_SMEM (NSTAGE * STAGE_B)           // 46080

__global__ __launch_bounds__(512, 2)
void gat_gemm_mma(const float* __restrict__ a_self, const float* __restrict__ a_neigh)
{
    extern __shared__ __align__(16) char dyn[];
    __shared__ float sm_as[UU], sm_an[UU];
    __shared__ float sred_fs[128], sred_fn[128];

    const int tid  = threadIdx.x;
    const int lane = tid & 31, wid = tid >> 5;
    const int bm = blockIdx.x * 128;
    const int hb = blockIdx.y;
    const int bn = hb * 64;
    const int mw = (wid >> 1) * 16;      // warp m offset (16 rows)
    const int nw = (wid & 1) * 32;       // warp n offset (32 cols)

    if (tid < UU) {
        sm_as[tid] = a_self[hb * UU + tid];
        sm_an[tid] = a_neigh[hb * UU + tid];
    }

    const uint32_t sbase = smem_u32(dyn);

    float acc[4][4];
#pragma unroll
    for (int nj = 0; nj < 4; nj++)
#pragma unroll
        for (int q = 0; q < 4; q++) acc[nj][q] = 0.f;

    // loader addressing (512 threads)
    const int a_row = tid >> 2, a_seg = tid & 3;            // A: 128 rows x 4 segs
    const int b_row = (tid & 255) >> 2, b_seg = tid & 3;    // B: 64 rows x 4 segs (threads <256)
    // ldmatrix lane addressing
    const int a_r = (lane & 15);
    const int a_k = (lane >> 4) * 8;
    const int b_c = ((lane >> 4) << 3) + (lane & 7);
    const int b_k = ((lane >> 3) & 1) * 8;

    auto issue = [&](int t) {
        const int st = t % NSTAGE;
        const uint32_t pA = sbase + st * STAGE_B;
        const uint32_t pB = pA + A_BYTES;
        const int kc = t * KCHUNK;
        {
            size_t go = (size_t)(bm + a_row) * FF + kc + a_seg * 8;
            uint32_t so = (uint32_t)(a_row * ROWB + a_seg * 16);
            cp16(pA + so, g_Xh + go);
        }
        if (tid < 256) {
            size_t go = (size_t)(bn + b_row) * FF + kc + b_seg * 8;
            uint32_t so = (uint32_t)(b_row * ROWB + b_seg * 16);
            cp16(pB + so, g_Wh + go);
        }
        CP_COMMIT();
    };

    const int T = FF / KCHUNK;    // 16
    issue(0);
    issue(1);
    for (int t = 0; t < T; t++) {
        CP_WAIT1();               // stage t complete
        __syncthreads();          // buffer (t+2)%3 now free (compute of t-1 done)
        if (t + 2 < T) issue(t + 2);

        const int st = t % NSTAGE;
        const uint32_t pA = sbase + st * STAGE_B;
        const uint32_t pB = pA + A_BYTES;

#pragma unroll
        for (int ks = 0; ks < 2; ks++) {
            const int kk = ks * 16;
            uint32_t ah[4];
            {
                uint32_t ao = (uint32_t)((mw + a_r) * ROWB + (kk + a_k) * 2);
                ldsm_x4(ah, pA + ao);
            }
            uint32_t bb[4][2];
#pragma unroll
            for (int bj = 0; bj < 2; bj++) {
                uint32_t bo = (uint32_t)((nw + bj * 16 + b_c) * ROWB + (kk + b_k) * 2);
                uint32_t r[4];
                ldsm_x4(r, pB + bo);
                bb[bj * 2][0] = r[0]; bb[bj * 2][1] = r[1];
                bb[bj * 2 + 1][0] = r[2]; bb[bj * 2 + 1][1] = r[3];
            }
#pragma unroll
            for (int nj = 0; nj < 4; nj++)
                mma16816(acc[nj], ah, bb[nj]);
        }
    }

    // ---- epilogue: store hfeat (fp16) + fused f_self/f_neigh ----
    const int er = lane >> 2;
    const int ec = (lane & 3) * 2;
    {
        const int row = bm + mw + er;
#pragma unroll
        for (int nj = 0; nj < 4; nj++) {
            const int col = bn + nw + nj * 8 + ec;
            *reinterpret_cast<__half2*>(g_hfeat + (size_t)row * HU + col) =
                __floats2half2_rn(acc[nj][0], acc[nj][1]);
            *reinterpret_cast<__half2*>(g_hfeat + (size_t)(row + 8) * HU + col) =
                __floats2half2_rn(acc[nj][2], acc[nj][3]);
        }
    }

    float fsv[2], fnv[2];
    {
        float fs0 = 0.f, fs1 = 0.f, fn0 = 0.f, fn1 = 0.f;
#pragma unroll
        for (int nj = 0; nj < 4; nj++) {
            const int c = nw + nj * 8 + ec;
            float as0 = sm_as[c], as1 = sm_as[c + 1];
            float an0 = sm_an[c], an1 = sm_an[c + 1];
            fs0 += acc[nj][0] * as0 + acc[nj][1] * as1;
            fs1 += acc[nj][2] * as0 + acc[nj][3] * as1;
            fn0 += acc[nj][0] * an0 + acc[nj][1] * an1;
            fn1 += acc[nj][2] * an0 + acc[nj][3] * an1;
        }
        fsv[0] = fs0; fsv[1] = fs1;
        fnv[0] = fn0; fnv[1] = fn1;
    }
#pragma unroll
    for (int rh = 0; rh < 2; rh++) {
        fsv[rh] += __shfl_xor_sync(0xFFFFFFFFu, fsv[rh], 1);
        fsv[rh] += __shfl_xor_sync(0xFFFFFFFFu, fsv[rh], 2);
        fnv[rh] += __shfl_xor_sync(0xFFFFFFFFu, fnv[rh], 1);
        fnv[rh] += __shfl_xor_sync(0xFFFFFFFFu, fnv[rh], 2);
    }
    if (nw == 0 && (lane & 3) == 0) {
        sred_fs[mw + er]     = fsv[0];
        sred_fs[mw + er + 8] = fsv[1];
        sred_fn[mw + er]     = fnv[0];
        sred_fn[mw + er + 8] = fnv[1];
    }
    __syncthreads();
    if (nw == 32 && (lane & 3) == 0) {
#pragma unroll
        for (int rh = 0; rh < 2; rh++) {
            const int r = mw + er + rh * 8;
            g_fs[(size_t)(bm + r) * HH + hb] = sred_fs[r] + fsv[rh];
            g_fn[(size_t)(bm + r) * HH + hb] = sred_fn[r] + fnv[rh];
        }
    }

#if __CUDA_ARCH__ >= 900
    // bound build_mask's completion by ours so the downstream aggregate
    // (which reads g_mask) keeps its ordering guarantee.
    cudaGridDependencySynchronize();
#endif
}

// ---------------- Kernel 3: aggregation (bitmask scan + fp16 gather) ----------------
__global__ __launch_bounds__(128)
void gat_aggregate(const float* __restrict__ bias,
                   float* __restrict__ out)
{
    const int i   = blockIdx.x;
    const int tid = threadIdx.x;            // 0..127
    const int lane = tid & 31, wid = tid >> 5;
    const int h   = tid >> 4;               // head (16 threads per head)
    const int sub = tid & 15;

    __shared__ int   sm_edges[EMAX];        // stores j<<9 (half-unit row offset)
    __shared__ float sm_w[HH][EMAX];
    __shared__ int   sm_psum[4];
    __shared__ float sm_fs[HH];

    if (tid < HH) sm_fs[tid] = g_fs[i * HH + tid];

    // ---- scan: 512 B bitmask per row ----
    uint32_t m = g_mask[i * 128 + tid];
    int cnt = __popc(m);
    int incl = cnt;
#pragma unroll
    for (int o = 1; o < 32; o <<= 1) {
        int nv = __shfl_up_sync(0xFFFFFFFFu, incl, o);
        if (lane >= o) incl += nv;
    }
    if (lane == 31) sm_psum[wid] = incl;
    __syncthreads();
    if (tid == 0) {
        int s = 0;
#pragma unroll
        for (int w = 0; w < 4; w++) { int v = sm_psum[w]; sm_psum[w] = s + v; s += v; }
    }
    __syncthreads();
    {
        int base = (wid ? sm_psum[wid - 1] : 0) + incl - cnt;
        int c0 = tid * 32;
        uint32_t mm = m;
        while (mm) {
            int b = __ffs(mm) - 1;
            mm &= mm - 1;
            sm_edges[min(base, EMAX - 1)] = (c0 + b) << 9;
            base++;
        }
    }
    __syncthreads();
    const int E = min(sm_psum[3], EMAX);

    // ---- weight phase: all E edges, all 8 heads, one pass ----
    for (int e = tid; e < E; e += 128) {
        int j8 = sm_edges[e] >> 6;          // j*8
        float4 f0 = *reinterpret_cast<const float4*>(g_fn + j8);
        float4 f1 = *reinterpret_cast<const float4*>(g_fn + j8 + 4);
        float fn8[8] = {f0.x, f0.y, f0.z, f0.w, f1.x, f1.y, f1.z, f1.w};
#pragma unroll
        for (int hh = 0; hh < HH; hh++) {
            float x = sm_fs[hh] + fn8[hh];
            x = x > 0.f ? x : LRELU * x;
            sm_w[hh][e] = __expf(x);
        }
    }
    __syncthreads();

    // ---- den partials ----
    float den = 0.f;
    for (int e = sub; e < E; e += 16) den += sm_w[h][e];

    // ---- gather-FMA over fp16 rows, unroll 8 ----
    const __half* hb = g_hfeat + tid * 4;   // thread's 4 columns
    float4 acc = make_float4(0.f, 0.f, 0.f, 0.f);
    int e = 0;
    for (; e + 8 <= E; e += 8) {
        int   o[8];
        float w[8];
        uint2 u[8];
#pragma unroll
        for (int q = 0; q < 8; q++) { o[q] = sm_edges[e + q]; w[q] = sm_w[h][e + q]; }
#pragma unroll
        for (int q = 0; q < 8; q++) u[q] = *reinterpret_cast<const uint2*>(hb + o[q]);
#pragma unroll
        for (int q = 0; q < 8; q++) {
            float2 pa = __half22float2(*reinterpret_cast<__half2*>(&u[q].x));
            float2 pb = __half22float2(*reinterpret_cast<__half2*>(&u[q].y));
            acc.x = fmaf(w[q], pa.x, acc.x); acc.y = fmaf(w[q], pa.y, acc.y);
            acc.z = fmaf(w[q], pb.x, acc.z); acc.w = fmaf(w[q], pb.y, acc.w);
        }
    }
    for (; e < E; e++) {
        int o0 = sm_edges[e];
        float w0 = sm_w[h][e];
        uint2 u0 = *reinterpret_cast<const uint2*>(hb + o0);
        float2 pa = __half22float2(*reinterpret_cast<__half2*>(&u0.x));
        float2 pb = __half22float2(*reinterpret_cast<__half2*>(&u0.y));
        acc.x = fmaf(w0, pa.x, acc.x); acc.y = fmaf(w0, pa.y, acc.y);
        acc.z = fmaf(w0, pb.x, acc.z); acc.w = fmaf(w0, pb.y, acc.w);
    }

    // segment-reduce den over the 16 lanes of this head
#pragma unroll
    for (int o = 8; o; o >>= 1) den += __shfl_xor_sync(0xFFFFFFFFu, den, o);
    const float rden = 1.f / den;

    float4 b4 = *reinterpret_cast<const float4*>(bias + tid * 4);
    float4 r;
    r.x = fmaf(acc.x, rden, b4.x); r.y = fmaf(acc.y, rden, b4.y);
    r.z = fmaf(acc.z, rden, b4.z); r.w = fmaf(acc.w, rden, b4.w);
    r.x = r.x > 0.f ? r.x : 0.f;
    r.y = r.y > 0.f ? r.y : 0.f;
    r.z = r.z > 0.f ? r.z : 0.f;
    r.w = r.w > 0.f ? r.w : 0.f;
    *reinterpret_cast<float4*>(out + (size_t)i * HU + tid * 4) = r;
}

// ---------------- launch ----------------
extern "C" void kernel_launch(void* const* d_in, const int* in_sizes, int n_in,
                              void* d_out, int out_size)
{
    const float* X       = (const float*)d_in[0];
    const float* A       = (const float*)d_in[2];
    const float* W       = (const float*)d_in[3];
    const float* a_self  = (const float*)d_in[4];
    const float* a_neigh = (const float*)d_in[5];
    const float* bias    = (const float*)d_in[6];
    float* out = (float*)d_out;

    cudaFuncSetAttribute(gat_gemm_mma, cudaFuncAttributeMaxDynamicSharedMemorySize, GEMM_SMEM);

    split_X_k<<<NN * FF / 4 / 256, 256>>>(X);
    split_W_k<<<dim3(FF / 32, HU / 32), 256>>>(W);
    build_mask<<<1024, 256>>>(A);

    // GEMM overlaps build_mask via programmatic dependent launch (no data dep).
    {
        cudaLaunchConfig_t cfg = {};
        cfg.gridDim = dim3(NN / 128, HU / 64, 1);
        cfg.blockDim = dim3(512, 1, 1);
        cfg.dynamicSmemBytes = GEMM_SMEM;
        cfg.stream = 0;
        cudaLaunchAttribute attrs[1];
        attrs[0].id = cudaLaunchAttributeProgrammaticStreamSerialization;
        attrs[0].val.programmaticStreamSerializationAllowed = 1;
        cfg.attrs = attrs;
        cfg.numAttrs = 1;
        cudaLaunchKernelEx(&cfg, gat_gemm_mma, a_self, a_neigh);
    }

    gat_aggregate<<<NN, 128>>>(bias, out);
}

// round 17
// speedup vs baseline: 1.3702x; 1.0740x over previous
#include <cuda_runtime.h>
#include <cuda_bf16.h>
#include <cuda_fp16.h>
#include <cstdint>

#define NN   4096
#define FF   512
#define UU   64
#define HH   8
#define HU   (HH*UU)     // 512
#define LRELU 0.2f
#define EMAX 256         // max edges/row (mean 42, 33-sigma safe; writes clamped)

// ---------------- scratch ----------------
__device__ __half g_hfeat[NN * HU];           // [N, H*U] fp16, 4 MB (L2-resident)
__device__ float g_fs[NN * HH];
__device__ float g_fn[NN * HH];
__device__ uint32_t g_mask[NN * 128];         // adjacency bitmask, 2 MB
__device__ __half g_Xh[NN * FF];              // X fp16
__device__ __half g_Wh[HU * FF];              // W^T fp16 [c][k]

// ---------------- helpers ----------------
__device__ __forceinline__ uint32_t smem_u32(const void* p) {
    uint32_t a;
    asm("{ .reg .u64 t; cvta.to.shared.u64 t, %1; cvt.u32.u64 %0, t; }" : "=r"(a) : "l"(p));
    return a;
}
__device__ __forceinline__ void ldsm_x4(uint32_t* r, uint32_t addr) {
    asm volatile("ldmatrix.sync.aligned.m8n8.x4.shared.b16 {%0,%1,%2,%3}, [%4];"
        : "=r"(r[0]), "=r"(r[1]), "=r"(r[2]), "=r"(r[3]) : "r"(addr));
}
__device__ __forceinline__ void mma16816(float* c, const uint32_t* a, const uint32_t* b) {
    asm volatile("mma.sync.aligned.m16n8k16.row.col.f32.f16.f16.f32 "
        "{%0,%1,%2,%3}, {%4,%5,%6,%7}, {%8,%9}, {%0,%1,%2,%3};"
        : "+f"(c[0]), "+f"(c[1]), "+f"(c[2]), "+f"(c[3])
        : "r"(a[0]), "r"(a[1]), "r"(a[2]), "r"(a[3]), "r"(b[0]), "r"(b[1]));
}
__device__ __forceinline__ void cp16(uint32_t dst, const void* src) {
    asm volatile("cp.async.cg.shared.global [%0], [%1], 16;" :: "r"(dst), "l"(src));
}
#define CP_COMMIT() asm volatile("cp.async.commit_group;" ::: "memory")
#define CP_WAIT1()  asm volatile("cp.async.wait_group 1;" ::: "memory")
#define CP_WAIT0()  asm volatile("cp.async.wait_group 0;" ::: "memory")

// ---------------- preprocess (fused): X -> fp16 ; W -> W^T fp16 ----------------
// blocks [0, 2048): X elementwise; blocks [2048, 2304): W transpose tiles
__global__ __launch_bounds__(256)
void preprocess_k(const float* __restrict__ X, const float* __restrict__ W)
{
    if (blockIdx.x < 2048) {
        int idx = blockIdx.x * 256 + threadIdx.x;
        float4 v = reinterpret_cast<const float4*>(X)[idx];
        __half2* ph = reinterpret_cast<__half2*>(g_Xh);
        ph[idx * 2]     = __floats2half2_rn(v.x, v.y);
        ph[idx * 2 + 1] = __floats2half2_rn(v.z, v.w);
    } else {
        __shared__ float t[32][33];
        const int b  = blockIdx.x - 2048;          // 0..255
        const int k0 = (b & 15) * 32;
        const int c0 = (b >> 4) * 32;
        const int h  = c0 >> 6;
        const int ub = c0 & 63;
        const int tx = threadIdx.x & 31, ty = threadIdx.x >> 5;

        for (int kk = ty; kk < 32; kk += 8)
            t[kk][tx] = W[(size_t)h * FF * UU + (size_t)(k0 + kk) * UU + ub + tx];
        __syncthreads();
        for (int cc = ty; cc < 32; cc += 8)
            g_Wh[(size_t)(c0 + cc) * FF + k0 + tx] = __float2half_rn(t[tx][cc]);
    }
}

// ---------------- Kernel 0: A -> bitmask (streaming, PDL primary) ----------------
__global__ __launch_bounds__(256)
void build_mask(const float* __restrict__ A)
{
#if __CUDA_ARCH__ >= 900
    cudaTriggerProgrammaticLaunchCompletion();   // let the GEMM launch now
#endif
#pragma unroll
    for (int it = 0; it < 2; it++) {
        int gid = (blockIdx.x * 2 + it) * 256 + threadIdx.x;   // 0 .. NN*128-1
        const float4* p = reinterpret_cast<const float4*>(A) + (size_t)gid * 8;
        uint32_t m = 0;
#pragma unroll
        for (int q = 0; q < 8; q++) {
            float4 v = p[q];
            m |= (uint32_t)(v.x != 0.f) << (q * 4);
            m |= (uint32_t)(v.y != 0.f) << (q * 4 + 1);
            m |= (uint32_t)(v.z != 0.f) << (q * 4 + 2);
            m |= (uint32_t)(v.w != 0.f) << (q * 4 + 3);
        }
        g_mask[gid] = m;
    }
}

// ---------------- Kernel 1: fp16 GEMM + fused f_self/f_neigh (PDL secondary) ----------------
// 512 threads / 16 warps, warp tile 16x32, KCHUNK=64, 3-stage cp.async, 2-ahead.
#define KCHUNK   64
#define ROWB     144                           // 128 data + 16 pad (odd 16-multiple)
#define A_BYTES  (128 * ROWB)                  // 18432
#define B_BYTES  (64 * ROWB)                   // 9216
#define STAGE_B  (A_BYTES + B_BYTES)           // 27648
#define NSTAGE   3
#define GEMM_SMEM (NSTAGE * STAGE_B)           // 82944

__global__ __launch_bounds__(512, 2)
void gat_gemm_mma(const float* __restrict__ a_self, const float* __restrict__ a_neigh)
{
    extern __shared__ __align__(16) char dyn[];
    __shared__ float sm_as[UU], sm_an[UU];
    __shared__ float sred_fs[128], sred_fn[128];

    const int tid  = threadIdx.x;
    const int lane = tid & 31, wid = tid >> 5;
    const int bm = blockIdx.x * 128;
    const int hb = blockIdx.y;
    const int bn = hb * 64;
    const int mw = (wid >> 1) * 16;      // warp m offset (16 rows)
    const int nw = (wid & 1) * 32;       // warp n offset (32 cols)

    if (tid < UU) {
        sm_as[tid] = a_self[hb * UU + tid];
        sm_an[tid] = a_neigh[hb * UU + tid];
    }

    const uint32_t sbase = smem_u32(dyn);

    float acc[4][4];
#pragma unroll
    for (int nj = 0; nj < 4; nj++)
#pragma unroll
        for (int q = 0; q < 4; q++) acc[nj][q] = 0.f;

    // loader addressing: A 128 rows x 8 segs (1024 chunks, 2/thread); B 64x8 (512, 1/thread)
    const int b_rowL = tid >> 3, b_segL = tid & 7;
    // ldmatrix lane addressing
    const int a_r = (lane & 15);
    const int a_k = (lane >> 4) * 8;
    const int b_c = ((lane >> 4) << 3) + (lane & 7);
    const int b_k = ((lane >> 3) & 1) * 8;

    auto issue = [&](int t) {
        const int st = t % NSTAGE;
        const uint32_t pA = sbase + st * STAGE_B;
        const uint32_t pB = pA + A_BYTES;
        const int kc = t * KCHUNK;
#pragma unroll
        for (int it = 0; it < 2; it++) {
            int q = tid + it * 512;
            int row = q >> 3, seg = q & 7;
            size_t go = (size_t)(bm + row) * FF + kc + seg * 8;
            uint32_t so = (uint32_t)(row * ROWB + seg * 16);
            cp16(pA + so, g_Xh + go);
        }
        {
            size_t go = (size_t)(bn + b_rowL) * FF + kc + b_segL * 8;
            uint32_t so = (uint32_t)(b_rowL * ROWB + b_segL * 16);
            cp16(pB + so, g_Wh + go);
        }
        CP_COMMIT();
    };

    const int T = FF / KCHUNK;    // 8
    issue(0);
    issue(1);
    for (int t = 0; t < T; t++) {
        CP_WAIT1();               // stage t complete
        __syncthreads();          // buffer (t+2)%3 now free
        if (t + 2 < T) issue(t + 2);

        const int st = t % NSTAGE;
        const uint32_t pA = sbase + st * STAGE_B;
        const uint32_t pB = pA + A_BYTES;

#pragma unroll
        for (int ks = 0; ks < 4; ks++) {
            const int kk = ks * 16;
            uint32_t ah[4];
            {
                uint32_t ao = (uint32_t)((mw + a_r) * ROWB + (kk + a_k) * 2);
                ldsm_x4(ah, pA + ao);
            }
            uint32_t bb[4][2];
#pragma unroll
            for (int bj = 0; bj < 2; bj++) {
                uint32_t bo = (uint32_t)((nw + bj * 16 + b_c) * ROWB + (kk + b_k) * 2);
                uint32_t r[4];
                ldsm_x4(r, pB + bo);
                bb[bj * 2][0] = r[0]; bb[bj * 2][1] = r[1];
                bb[bj * 2 + 1][0] = r[2]; bb[bj * 2 + 1][1] = r[3];
            }
#pragma unroll
            for (int nj = 0; nj < 4; nj++)
                mma16816(acc[nj], ah, bb[nj]);
        }
    }

    // ---- epilogue: store hfeat (fp16) + fused f_self/f_neigh ----
    const int er = lane >> 2;
    const int ec = (lane & 3) * 2;
    {
        const int row = bm + mw + er;
#pragma unroll
        for (int nj = 0; nj < 4; nj++) {
            const int col = bn + nw + nj * 8 + ec;
            *reinterpret_cast<__half2*>(g_hfeat + (size_t)row * HU + col) =
                __floats2half2_rn(acc[nj][0], acc[nj][1]);
            *reinterpret_cast<__half2*>(g_hfeat + (size_t)(row + 8) * HU + col) =
                __floats2half2_rn(acc[nj][2], acc[nj][3]);
        }
    }

    float fsv[2], fnv[2];
    {
        float fs0 = 0.f, fs1 = 0.f, fn0 = 0.f, fn1 = 0.f;
#pragma unroll
        for (int nj = 0; nj < 4; nj++) {
            const int c = nw + nj * 8 + ec;
            float as0 = sm_as[c], as1 = sm_as[c + 1];
            float an0 = sm_an[c], an1 = sm_an[c + 1];
            fs0 += acc[nj][0] * as0 + acc[nj][1] * as1;
            fs1 += acc[nj][2] * as0 + acc[nj][3] * as1;
            fn0 += acc[nj][0] * an0 + acc[nj][1] * an1;
            fn1 += acc[nj][2] * an0 + acc[nj][3] * an1;
        }
        fsv[0] = fs0; fsv[1] = fs1;
        fnv[0] = fn0; fnv[1] = fn1;
    }
#pragma unroll
    for (int rh = 0; rh < 2; rh++) {
        fsv[rh] += __shfl_xor_sync(0xFFFFFFFFu, fsv[rh], 1);
        fsv[rh] += __shfl_xor_sync(0xFFFFFFFFu, fsv[rh], 2);
        fnv[rh] += __shfl_xor_sync(0xFFFFFFFFu, fnv[rh], 1);
        fnv[rh] += __shfl_xor_sync(0xFFFFFFFFu, fnv[rh], 2);
    }
    if (nw == 0 && (lane & 3) == 0) {
        sred_fs[mw + er]     = fsv[0];
        sred_fs[mw + er + 8] = fsv[1];
        sred_fn[mw + er]     = fnv[0];
        sred_fn[mw + er + 8] = fnv[1];
    }
    __syncthreads();
    if (nw == 32 && (lane & 3) == 0) {
#pragma unroll
        for (int rh = 0; rh < 2; rh++) {
            const int r = mw + er + rh * 8;
            g_fs[(size_t)(bm + r) * HH + hb] = sred_fs[r] + fsv[rh];
            g_fn[(size_t)(bm + r) * HH + hb] = sred_fn[r] + fnv[rh];
        }
    }

#if __CUDA_ARCH__ >= 900
    // bound build_mask's completion by ours so the downstream aggregate
    // (which reads g_mask) keeps its ordering guarantee.
    cudaGridDependencySynchronize();
#endif
}

// ---------------- Kernel 3: aggregation (bitmask scan + fp16 gather) ----------------
__global__ __launch_bounds__(128)
void gat_aggregate(const float* __restrict__ bias,
                   float* __restrict__ out)
{
    const int i   = blockIdx.x;
    const int tid = threadIdx.x;            // 0..127
    const int lane = tid & 31, wid = tid >> 5;
    const int h   = tid >> 4;               // head (16 threads per head)
    const int sub = tid & 15;

    __shared__ int   sm_edges[EMAX];        // stores j<<9 (half-unit row offset)
    __shared__ float sm_w[HH][EMAX];
    __shared__ int   sm_psum[4];
    __shared__ float sm_fs[HH];

    if (tid < HH) sm_fs[tid] = g_fs[i * HH + tid];

    // ---- scan: 512 B bitmask per row ----
    uint32_t m = g_mask[i * 128 + tid];
    int cnt = __popc(m);
    int incl = cnt;
#pragma unroll
    for (int o = 1; o < 32; o <<= 1) {
        int nv = __shfl_up_sync(0xFFFFFFFFu, incl, o);
        if (lane >= o) incl += nv;
    }
    if (lane == 31) sm_psum[wid] = incl;
    __syncthreads();
    if (tid == 0) {
        int s = 0;
#pragma unroll
        for (int w = 0; w < 4; w++) { int v = sm_psum[w]; sm_psum[w] = s + v; s += v; }
    }
    __syncthreads();
    {
        int base = (wid ? sm_psum[wid - 1] : 0) + incl - cnt;
        int c0 = tid * 32;
        uint32_t mm = m;
        while (mm) {
            int b = __ffs(mm) - 1;
            mm &= mm - 1;
            sm_edges[min(base, EMAX - 1)] = (c0 + b) << 9;
            base++;
        }
    }
    __syncthreads();
    const int E = min(sm_psum[3], EMAX);

    // ---- weight phase: all E edges, all 8 heads, one pass ----
    for (int e = tid; e < E; e += 128) {
        int j8 = sm_edges[e] >> 6;          // j*8
        float4 f0 = *reinterpret_cast<const float4*>(g_fn + j8);
        float4 f1 = *reinterpret_cast<const float4*>(g_fn + j8 + 4);
        float fn8[8] = {f0.x, f0.y, f0.z, f0.w, f1.x, f1.y, f1.z, f1.w};
#pragma unroll
        for (int hh = 0; hh < HH; hh++) {
            float x = sm_fs[hh] + fn8[hh];
            x = x > 0.f ? x : LRELU * x;
            sm_w[hh][e] = __expf(x);
        }
    }
    __syncthreads();

    // ---- den partials ----
    float den = 0.f;
    for (int e = sub; e < E; e += 16) den += sm_w[h][e];

    // ---- gather-FMA over fp16 rows, unroll 8 ----
    const __half* hb = g_hfeat + tid * 4;   // thread's 4 columns
    float4 acc = make_float4(0.f, 0.f, 0.f, 0.f);
    int e = 0;
    for (; e + 8 <= E; e += 8) {
        int   o[8];
        float w[8];
        uint2 u[8];
#pragma unroll
        for (int q = 0; q < 8; q++) { o[q] = sm_edges[e + q]; w[q] = sm_w[h][e + q]; }
#pragma unroll
        for (int q = 0; q < 8; q++) u[q] = *reinterpret_cast<const uint2*>(hb + o[q]);
#pragma unroll
        for (int q = 0; q < 8; q++) {
            float2 pa = __half22float2(*reinterpret_cast<__half2*>(&u[q].x));
            float2 pb = __half22float2(*reinterpret_cast<__half2*>(&u[q].y));
            acc.x = fmaf(w[q], pa.x, acc.x); acc.y = fmaf(w[q], pa.y, acc.y);
            acc.z = fmaf(w[q], pb.x, acc.z); acc.w = fmaf(w[q], pb.y, acc.w);
        }
    }
    for (; e < E; e++) {
        int o0 = sm_edges[e];
        float w0 = sm_w[h][e];
        uint2 u0 = *reinterpret_cast<const uint2*>(hb + o0);
        float2 pa = __half22float2(*reinterpret_cast<__half2*>(&u0.x));
        float2 pb = __half22float2(*reinterpret_cast<__half2*>(&u0.y));
        acc.x = fmaf(w0, pa.x, acc.x); acc.y = fmaf(w0, pa.y, acc.y);
        acc.z = fmaf(w0, pb.x, acc.z); acc.w = fmaf(w0, pb.y, acc.w);
    }

    // segment-reduce den over the 16 lanes of this head
#pragma unroll
    for (int o = 8; o; o >>= 1) den += __shfl_xor_sync(0xFFFFFFFFu, den, o);
    const float rden = 1.f / den;

    float4 b4 = *reinterpret_cast<const float4*>(bias + tid * 4);
    float4 r;
    r.x = fmaf(acc.x, rden, b4.x); r.y = fmaf(acc.y, rden, b4.y);
    r.z = fmaf(acc.z, rden, b4.z); r.w = fmaf(acc.w, rden, b4.w);
    r.x = r.x > 0.f ? r.x : 0.f;
    r.y = r.y > 0.f ? r.y : 0.f;
    r.z = r.z > 0.f ? r.z : 0.f;
    r.w = r.w > 0.f ? r.w : 0.f;
    *reinterpret_cast<float4*>(out + (size_t)i * HU + tid * 4) = r;
}

// ---------------- launch ----------------
extern "C" void kernel_launch(void* const* d_in, const int* in_sizes, int n_in,
                              void* d_out, int out_size)
{
    const float* X       = (const float*)d_in[0];
    const float* A       = (const float*)d_in[2];
    const float* W       = (const float*)d_in[3];
    const float* a_self  = (const float*)d_in[4];
    const float* a_neigh = (const float*)d_in[5];
    const float* bias    = (const float*)d_in[6];
    float* out = (float*)d_out;

    cudaFuncSetAttribute(gat_gemm_mma, cudaFuncAttributeMaxDynamicSharedMemorySize, GEMM_SMEM);

    preprocess_k<<<2304, 256>>>(X, W);
    build_mask<<<1024, 256>>>(A);

    // GEMM overlaps build_mask via programmatic dependent launch (no data dep).
    {
        cudaLaunchConfig_t cfg = {};
        cfg.gridDim = dim3(NN / 128, HU / 64, 1);
        cfg.blockDim = dim3(512, 1, 1);
        cfg.dynamicSmemBytes = GEMM_SMEM;
        cfg.stream = 0;
        cudaLaunchAttribute attrs[1];
        attrs[0].id = cudaLaunchAttributeProgrammaticStreamSerialization;
        attrs[0].val.programmaticStreamSerializationAllowed = 1;
        cfg.attrs = attrs;
        cfg.numAttrs = 1;
        cudaLaunchKernelEx(&cfg, gat_gemm_mma, a_self, a_neigh);
    }

    gat_aggregate<<<NN, 128>>>(bias, out);
}